// round 4
// baseline (speedup 1.0000x reference)
#include <cuda_runtime.h>

// GAE backward scan, (B=8192, T=256, A=4), fp32.
//   c_t = gamma*lambda*nd_t ; d_t = r_t + gamma*nv_t*nd_t - v_t
//   gae_t = d_t + c_t * gae_{t+1}  (gae_T = 0);  adv = gae, ret = gae + v.
// Output: [adv (B*T*A) | ret (B*T*A)].
//
// R4: one warp per batch. Linear recurrence solved as an affine (Sc, Off)
//     backward inclusive scan across lanes (5 shfl_down steps), 8 rounds of
//     32 t-steps. No smem, no barriers, all lanes busy, coalesced float4 I/O.

#define GAMMA_F 0.99f
#define GL_F    (0.99f * 0.95f)

constexpr int B     = 8192;
constexpr int T     = 256;
constexpr int A     = 4;
constexpr int ROW4  = T * A / 4;    // 256 float4 per batch row
constexpr int WPB   = 4;            // independent warps per block
constexpr int THREADS = 32 * WPB;
constexpr int ROUNDS  = T / 32;     // 8

__global__ __launch_bounds__(THREADS)
void gae_kernel(const float4* __restrict__ reward,
                const float4* __restrict__ term,
                const float4* __restrict__ value,
                const float4* __restrict__ nxtval,
                float4* __restrict__ adv_out,
                float4* __restrict__ ret_out)
{
    const int lane = threadIdx.x & 31;
    const int warp = threadIdx.x >> 5;
    const int b    = blockIdx.x * WPB + warp;
    const int base = b * ROW4 + lane;      // lane's float4 slot within round 0

    float carry0 = 0.f, carry1 = 0.f, carry2 = 0.f, carry3 = 0.f;

    // prologue: prefetch round ROUNDS-1
    int gp = base + 32 * (ROUNDS - 1);
    float4 pr  = reward[gp];
    float4 ptm = term[gp];
    float4 pv  = value[gp];
    float4 pnv = nxtval[gp];

    #pragma unroll 1
    for (int k = ROUNDS - 1; k >= 0; k--) {
        const float4 cr  = pr;
        const float4 ctm = ptm;
        const float4 cv  = pv;
        const float4 cnv = pnv;

        // issue next round's loads; latency overlaps this round's scan
        if (k > 0) {
            const int gn = base + 32 * (k - 1);
            pr  = reward[gn];
            ptm = term[gn];
            pv  = value[gn];
            pnv = nxtval[gn];
        }

        const float* rp = &cr.x;
        const float* tp = &ctm.x;
        const float* vp = &cv.x;
        const float* np = &cnv.x;
        float carry[4] = {carry0, carry1, carry2, carry3};
        float gae[4];

        #pragma unroll
        for (int j = 0; j < 4; j++) {
            const float nd = 1.0f - tp[j];
            float Sc  = GL_F * nd;                               // c_t
            float Off = fmaf(GAMMA_F * np[j], nd, rp[j]) - vp[j]; // d_t

            // backward inclusive affine scan over lanes (lane l -> compose l..31)
            #pragma unroll
            for (int off = 1; off < 32; off <<= 1) {
                const float ScU  = __shfl_down_sync(0xffffffffu, Sc,  off);
                const float OffU = __shfl_down_sync(0xffffffffu, Off, off);
                if (lane + off < 32) {
                    Off = fmaf(Sc, OffU, Off);
                    Sc *= ScU;
                }
            }
            gae[j]   = fmaf(Sc, carry[j], Off);
            carry[j] = __shfl_sync(0xffffffffu, gae[j], 0);  // gae at t = 32k
        }
        carry0 = carry[0]; carry1 = carry[1]; carry2 = carry[2]; carry3 = carry[3];

        const int go = base + 32 * k;
        float4 ad, rt;
        ad.x = gae[0]; ad.y = gae[1]; ad.z = gae[2]; ad.w = gae[3];
        rt.x = gae[0] + vp[0]; rt.y = gae[1] + vp[1];
        rt.z = gae[2] + vp[2]; rt.w = gae[3] + vp[3];
        adv_out[go] = ad;
        ret_out[go] = rt;
    }
}

extern "C" void kernel_launch(void* const* d_in, const int* in_sizes, int n_in,
                              void* d_out, int out_size)
{
    const float4* reward = (const float4*)d_in[0];
    const float4* term   = (const float4*)d_in[1];
    const float4* value  = (const float4*)d_in[2];
    const float4* nxtval = (const float4*)d_in[3];

    float* out = (float*)d_out;
    float4* adv = (float4*)out;
    float4* ret = (float4*)(out + (size_t)B * T * A);

    gae_kernel<<<B / WPB, THREADS>>>(reward, term, value, nxtval, adv, ret);
}

// round 5
// speedup vs baseline: 1.1115x; 1.1115x over previous
#include <cuda_runtime.h>

// GAE backward scan, (B=8192, T=256, A=4), fp32.
//   c_t = gamma*lambda*nd_t ; d_t = r_t + gamma*nv_t*nd_t - v_t
//   gae_t = d_t + c_t*gae_{t+1}  (gae_T = 0);  adv = gae, ret = gae + v.
// Output: [adv (B*T*A) | ret (B*T*A)].
//
// R5: depth-2 register pipeline (8 LDG.128 in flight per warp), fully
//     unrolled rounds, streaming cache hints (__ldcs/__stcs). Warp affine
//     scan retained (proven equal-speed, no smem, no barriers).

#define GAMMA_F 0.99f
#define GL_F    (0.99f * 0.95f)

constexpr int B     = 8192;
constexpr int T     = 256;
constexpr int A     = 4;
constexpr int ROW4  = T * A / 4;    // 256 float4 per batch row
constexpr int WPB   = 4;            // independent warps per block
constexpr int THREADS = 32 * WPB;
constexpr int ROUNDS  = T / 32;     // 8

struct Chunk { float4 r, tm, v, nv; };

__device__ __forceinline__ Chunk ld_round(const float4* __restrict__ reward,
                                          const float4* __restrict__ term,
                                          const float4* __restrict__ value,
                                          const float4* __restrict__ nxtval,
                                          int g)
{
    Chunk c;
    c.r  = __ldcs(reward + g);
    c.tm = __ldcs(term   + g);
    c.v  = __ldcs(value  + g);
    c.nv = __ldcs(nxtval + g);
    return c;
}

__global__ __launch_bounds__(THREADS)
void gae_kernel(const float4* __restrict__ reward,
                const float4* __restrict__ term,
                const float4* __restrict__ value,
                const float4* __restrict__ nxtval,
                float4* __restrict__ adv_out,
                float4* __restrict__ ret_out)
{
    const int lane = threadIdx.x & 31;
    const int warp = threadIdx.x >> 5;
    const int b    = blockIdx.x * WPB + warp;
    const int base = b * ROW4 + lane;      // lane's float4 slot within round 0

    float carry[4] = {0.f, 0.f, 0.f, 0.f};

    // depth-2 prologue: rounds 7 and 6 both in flight
    Chunk buf[2];
    buf[(ROUNDS - 1) & 1] = ld_round(reward, term, value, nxtval,
                                     base + 32 * (ROUNDS - 1));
    buf[(ROUNDS - 2) & 1] = ld_round(reward, term, value, nxtval,
                                     base + 32 * (ROUNDS - 2));

    #pragma unroll
    for (int k = ROUNDS - 1; k >= 0; k--) {
        const int s = k & 1;

        const float4 cr  = buf[s].r;
        const float4 ctm = buf[s].tm;
        const float4 cv  = buf[s].v;
        const float4 cnv = buf[s].nv;

        // refill this slot two rounds ahead; latency overlaps two scans
        if (k >= 2)
            buf[s] = ld_round(reward, term, value, nxtval, base + 32 * (k - 2));

        const float* rp = &cr.x;
        const float* tp = &ctm.x;
        const float* vp = &cv.x;
        const float* np = &cnv.x;
        float gae[4];

        #pragma unroll
        for (int j = 0; j < 4; j++) {
            const float nd = 1.0f - tp[j];
            float Sc  = GL_F * nd;                                 // c_t
            float Off = fmaf(GAMMA_F * np[j], nd, rp[j]) - vp[j];  // d_t

            // backward inclusive affine scan over lanes
            #pragma unroll
            for (int off = 1; off < 32; off <<= 1) {
                const float ScU  = __shfl_down_sync(0xffffffffu, Sc,  off);
                const float OffU = __shfl_down_sync(0xffffffffu, Off, off);
                if (lane + off < 32) {
                    Off = fmaf(Sc, OffU, Off);
                    Sc *= ScU;
                }
            }
            gae[j]   = fmaf(Sc, carry[j], Off);
            carry[j] = __shfl_sync(0xffffffffu, gae[j], 0);  // gae at t = 32k
        }

        const int go = base + 32 * k;
        float4 ad, rt;
        ad.x = gae[0]; ad.y = gae[1]; ad.z = gae[2]; ad.w = gae[3];
        rt.x = gae[0] + vp[0]; rt.y = gae[1] + vp[1];
        rt.z = gae[2] + vp[2]; rt.w = gae[3] + vp[3];
        __stcs(adv_out + go, ad);
        __stcs(ret_out + go, rt);
    }
}

extern "C" void kernel_launch(void* const* d_in, const int* in_sizes, int n_in,
                              void* d_out, int out_size)
{
    const float4* reward = (const float4*)d_in[0];
    const float4* term   = (const float4*)d_in[1];
    const float4* value  = (const float4*)d_in[2];
    const float4* nxtval = (const float4*)d_in[3];

    float* out = (float*)d_out;
    float4* adv = (float4*)out;
    float4* ret = (float4*)(out + (size_t)B * T * A);

    gae_kernel<<<B / WPB, THREADS>>>(reward, term, value, nxtval, adv, ret);
}